// round 14
// baseline (speedup 1.0000x reference)
#include <cuda_runtime.h>
#include <cuda_fp16.h>
#include <stdint.h>

#define HEADS   8
#define DHEAD   64
#define C_DIM   512
#define BATCH   2
#define HW      2304          // 48*48
#define BN      (BATCH*HEADS) // 16
#define KCH     128           // kv chunk rows in attention
#define NCH     (HW / KCH)    // 18
#define QT      256           // q-tile rows in attention

// Scratch (no cudaMalloc allowed). All fp16.
__device__ __align__(16) __half g_Q[BN * HW * DHEAD];
__device__ __align__(16) __half g_K[BN * HW * DHEAD];
__device__ __align__(16) __half g_V[BN * HW * DHEAD];
__device__ __align__(16) __half g_O[BN * HW * DHEAD];
__device__ __align__(16) __half g_Xt[BATCH * C_DIM * HW];         // X as fp16
__device__ __align__(16) __half g_Wt[3 * HEADS * DHEAD * C_DIM];  // Wq|Wk|Wv fp16
__device__ __align__(16) __half g_Wot[C_DIM * C_DIM];             // Wo fp16

#define NX   (BATCH * C_DIM * HW)        // 2359296
#define NW   (HEADS * DHEAD * C_DIM)     // 262144
#define NWO  (C_DIM * C_DIM)             // 262144
#define NCVT (NX + 3 * NW + NWO)

#define LOG2E 1.44269504088896340736f

// ---------------------------------------------------------------------------
// helpers
// ---------------------------------------------------------------------------
__device__ __forceinline__ uint32_t pack2(float a, float b) {
    __half2 h = __floats2half2_rn(a, b);
    return *(uint32_t*)&h;
}
__device__ __forceinline__ float ex2f(float x) {
    float y; asm("ex2.approx.f32 %0, %1;" : "=f"(y) : "f"(x)); return y;
}
__device__ __forceinline__ uint32_t ex2h2(uint32_t x) {
    uint32_t y; asm("ex2.approx.f16x2 %0, %1;" : "=r"(y) : "r"(x)); return y;
}
__device__ __forceinline__ void mma16(float* c, const uint32_t* a, const uint32_t* b) {
    asm volatile(
        "mma.sync.aligned.m16n8k16.row.col.f32.f16.f16.f32 "
        "{%0,%1,%2,%3}, {%4,%5,%6,%7}, {%8,%9}, {%0,%1,%2,%3};"
        : "+f"(c[0]), "+f"(c[1]), "+f"(c[2]), "+f"(c[3])
        : "r"(a[0]), "r"(a[1]), "r"(a[2]), "r"(a[3]), "r"(b[0]), "r"(b[1]));
}
__device__ __forceinline__ void mma16h(uint32_t* c, const uint32_t* a, const uint32_t* b) {
    asm volatile(
        "mma.sync.aligned.m16n8k16.row.col.f16.f16.f16.f16 "
        "{%0,%1}, {%2,%3,%4,%5}, {%6,%7}, {%0,%1};"
        : "+r"(c[0]), "+r"(c[1])
        : "r"(a[0]), "r"(a[1]), "r"(a[2]), "r"(a[3]), "r"(b[0]), "r"(b[1]));
}
__device__ __forceinline__ uint32_t su(const void* p) {
    return (uint32_t)__cvta_generic_to_shared(p);
}
__device__ __forceinline__ void ldmx4(uint32_t* r, uint32_t a) {
    asm volatile("ldmatrix.sync.aligned.m8n8.x4.shared.b16 {%0,%1,%2,%3}, [%4];"
                 : "=r"(r[0]), "=r"(r[1]), "=r"(r[2]), "=r"(r[3]) : "r"(a));
}
__device__ __forceinline__ void ldmx4t(uint32_t* r, uint32_t a) {
    asm volatile("ldmatrix.sync.aligned.m8n8.x4.trans.shared.b16 {%0,%1,%2,%3}, [%4];"
                 : "=r"(r[0]), "=r"(r[1]), "=r"(r[2]), "=r"(r[3]) : "r"(a));
}
__device__ __forceinline__ void cp16(uint32_t dst, const void* src) {
    asm volatile("cp.async.cg.shared.global [%0], [%1], 16;"
                 :: "r"(dst), "l"(src) : "memory");
}
#define CP_COMMIT() asm volatile("cp.async.commit_group;" ::: "memory")
#define CP_WAIT1()  asm volatile("cp.async.wait_group 1;" ::: "memory")

#define XS 72    // 64-wide rows: 64 + 8 pad (halfs)
#define XQ 136   // qkv X rows: 128 + 8 pad (halfs)

// ---------------------------------------------------------------------------
// Kernel 0: one-time fp16 conversion of X, Wq|Wk|Wv, Wo. 8 elems/thread.
// ---------------------------------------------------------------------------
__global__ __launch_bounds__(256) void cvt_kernel(
    const float* __restrict__ X,
    const float* __restrict__ Wq, const float* __restrict__ Wk,
    const float* __restrict__ Wv, const float* __restrict__ Wo)
{
    int i = (blockIdx.x * 256 + threadIdx.x) * 8;
    if (i >= NCVT) return;
    const float* src;
    __half* dst;
    int j;
    if (i < NX)               { src = X;  dst = g_Xt;           j = i; }
    else if (i < NX + NW)     { src = Wq; dst = g_Wt;           j = i - NX; }
    else if (i < NX + 2 * NW) { src = Wk; dst = g_Wt + NW;      j = i - NX - NW; }
    else if (i < NX + 3 * NW) { src = Wv; dst = g_Wt + 2 * NW;  j = i - NX - 2 * NW; }
    else                      { src = Wo; dst = g_Wot;          j = i - NX - 3 * NW; }
    float4 v0 = *(const float4*)&src[j];
    float4 v1 = *(const float4*)&src[j + 4];
    uint4 h = make_uint4(pack2(v0.x, v0.y), pack2(v0.z, v0.w),
                         pack2(v1.x, v1.y), pack2(v1.z, v1.w));
    *(uint4*)&dst[j] = h;
}

// ---------------------------------------------------------------------------
// Kernel 1: merged QKV projection (unchanged from R13).
// Tile 128(s) x 192(d), BK=64, 8 k-iters, 3-stage ring, 256 threads.
// ---------------------------------------------------------------------------
#define QKV_STG_H (64 * XQ + 3 * 64 * XS)       // 22528 halfs
#define QKV_SMEM_BYTES (3 * QKV_STG_H * 2)      // 135168

__global__ __launch_bounds__(256, 1) void qkv_kernel(
    const float* __restrict__ bq, const float* __restrict__ bk,
    const float* __restrict__ bv)
{
    extern __shared__ __half sm[];

    const int bn = blockIdx.y;
    const int b  = bn >> 3;
    const int n  = bn & 7;
    const int s0 = blockIdx.x * 128;

    const int tid    = threadIdx.x;
    const int wid    = tid >> 5;
    const int lane   = tid & 31;
    const int lg     = lane >> 2;
    const int lt     = lane & 3;
    const int warp_m = wid >> 1;
    const int warp_n = wid & 1;
    const int l7     = lane & 7;
    const int l8     = (lane >> 3) & 1;
    const int l16    = lane >> 4;
    const int g      = lane >> 3;
    const int gk     = (g & 1) << 3;
    const int gn     = (g >> 1) << 3;

    float acc[3][2][4][4] = {};

    auto Xst = [&](int st) { return sm + st * QKV_STG_H; };
    auto Wst = [&](int st, int w) { return sm + st * QKV_STG_H + 64 * XQ + w * 64 * XS; };

    auto load_chunk = [&](int st, int kc) {
        const int k0 = kc * 64;
        #pragma unroll
        for (int t = 0; t < 10; t++) {
            int idx = tid + t * 256;
            if (idx < 1024) {
                int kk = idx >> 4, seg = idx & 15;
                cp16(su(Xst(st) + kk * XQ + seg * 8),
                     &g_Xt[((size_t)b * C_DIM + k0 + kk) * HW + s0 + seg * 8]);
            } else {
                int j = idx - 1024;
                int w = j >> 9, r = j & 511;
                int d = r >> 3, seg = r & 7;
                cp16(su(Wst(st, w) + d * XS + seg * 8),
                     &g_Wt[(size_t)w * NW + ((size_t)n * DHEAD + d) * C_DIM + k0 + seg * 8]);
            }
        }
    };

    load_chunk(0, 0); CP_COMMIT();
    load_chunk(1, 1); CP_COMMIT();

    for (int kc = 0; kc < 8; kc++) {
        const int st = kc % 3;
        CP_WAIT1();
        __syncthreads();
        if (kc + 2 < 8) load_chunk((kc + 2) % 3, kc + 2);
        CP_COMMIT();

        #pragma unroll
        for (int ks = 0; ks < 4; ks++) {
            const int kb = ks * 16;
            uint32_t a[2][4];
            #pragma unroll
            for (int mi = 0; mi < 2; mi++)
                ldmx4t(a[mi], su(Xst(st) + (kb + l16 * 8 + l7) * XQ
                                 + warp_m * 32 + mi * 16 + l8 * 8));
            #pragma unroll
            for (int w = 0; w < 3; w++) {
                #pragma unroll
                for (int nt2 = 0; nt2 < 2; nt2++) {
                    uint32_t bfr[4];
                    ldmx4(bfr, su(Wst(st, w)
                                  + (warp_n * 32 + nt2 * 16 + gn + l7) * XS
                                  + kb + gk));
                    #pragma unroll
                    for (int mi = 0; mi < 2; mi++) {
                        mma16(acc[w][mi][nt2 * 2],     a[mi], bfr);
                        mma16(acc[w][mi][nt2 * 2 + 1], a[mi], bfr + 2);
                    }
                }
            }
        }
    }

    const float* bp[3] = {bq, bk, bv};
    __half* Outp[3] = {g_Q, g_K, g_V};
    #pragma unroll
    for (int w = 0; w < 3; w++) {
        const float scale = (w == 0) ? 0.125f * LOG2E : 1.0f;
        __half* Out = Outp[w];
        #pragma unroll
        for (int mi = 0; mi < 2; mi++) {
            const int row0 = s0 + warp_m * 32 + mi * 16 + lg;
            #pragma unroll
            for (int nt = 0; nt < 4; nt++) {
                int col = warp_n * 32 + nt * 8 + 2 * lt;
                float b0f = bp[w][n * DHEAD + col];
                float b1f = bp[w][n * DHEAD + col + 1];
                *(uint32_t*)&Out[((size_t)bn * HW + row0) * DHEAD + col] =
                    pack2((acc[w][mi][nt][0] + b0f) * scale,
                          (acc[w][mi][nt][1] + b1f) * scale);
                *(uint32_t*)&Out[((size_t)bn * HW + row0 + 8) * DHEAD + col] =
                    pack2((acc[w][mi][nt][2] + b0f) * scale,
                          (acc[w][mi][nt][3] + b1f) * scale);
            }
        }
    }
}

// ---------------------------------------------------------------------------
// Kernel 2: flash attention. 512 threads, QT=256 (16 warps x 16 rows),
// KCH=128 kv chunks (18 total), 3-stage ring. f16 S accumulators, log2
// softmax, P written in place over S, register-passed to PV.
// grid (9, 16) = 144 CTAs.
// ---------------------------------------------------------------------------
#define ATTN_STG_H (2 * KCH * XS)                 // 18432 halfs (K+V)
#define ATTN_SMEM_BYTES (3 * ATTN_STG_H * 2)      // 110592

__global__ __launch_bounds__(512, 1) void attn_kernel()
{
    extern __shared__ __half smA[];
    const int bn = blockIdx.y;
    const int q0 = blockIdx.x * QT;
    const int tid = threadIdx.x, wid = tid >> 5, lane = tid & 31;
    const int lg = lane >> 2, lt = lane & 3, l7 = lane & 7;
    const int g = lane >> 3, gk = (g & 1) << 3, gn = (g >> 1) << 3;
    const int qrow = q0 + wid * 16 + lg;

    auto Kst = [&](int st) { return smA + st * ATTN_STG_H; };
    auto Vst = [&](int st) { return smA + st * ATTN_STG_H + KCH * XS; };

    // ---- Q fragments register-resident (pre-scaled fp16, log2 domain) ----
    uint32_t qa[4][4];
    {
        const __half* Qb = &g_Q[((size_t)bn * HW + qrow) * DHEAD];
        #pragma unroll
        for (int ks = 0; ks < 4; ks++) {
            int k = ks * 16 + 2 * lt;
            qa[ks][0] = *(const uint32_t*)&Qb[k];
            qa[ks][1] = *(const uint32_t*)&Qb[8 * DHEAD + k];
            qa[ks][2] = *(const uint32_t*)&Qb[k + 8];
            qa[ks][3] = *(const uint32_t*)&Qb[8 * DHEAD + k + 8];
        }
    }

    auto load_chunk = [&](int st, int kt) {
        // K,V: 128 rows x 8 segs = 1024 each -> 2048 segs, 4/thread
        #pragma unroll
        for (int t = 0; t < 4; t++) {
            int idx = tid + t * 512;
            int r = (idx >> 3) & 127, seg = idx & 7;
            const __half* src = (idx < 1024 ? g_K : g_V)
                              + ((size_t)bn * HW + (size_t)kt * KCH + r) * DHEAD + seg * 8;
            cp16(su((idx < 1024 ? Kst(st) : Vst(st)) + r * XS + seg * 8), src);
        }
    };

    load_chunk(0, 0); CP_COMMIT();
    load_chunk(1, 1); CP_COMMIT();

    float o_acc[8][4] = {};
    float m0 = -1e30f, m8 = -1e30f, l0 = 0.0f, l8v = 0.0f;

    for (int kt = 0; kt < NCH; kt++) {
        const int st = kt % 3;
        CP_WAIT1();
        __syncthreads();
        if (kt + 2 < NCH) load_chunk((kt + 2) % 3, kt + 2);
        CP_COMMIT();

        // ---- S = Q @ K^T : warp m16 x n128, k=64, f16 accum ----
        uint32_t sf[16][2];
        #pragma unroll
        for (int nt = 0; nt < 16; nt++) { sf[nt][0] = 0u; sf[nt][1] = 0u; }
        #pragma unroll
        for (int ks = 0; ks < 4; ks++) {
            const int kb = ks * 16;
            #pragma unroll
            for (int nt2 = 0; nt2 < 8; nt2++) {
                uint32_t bfr[4];
                ldmx4(bfr, su(Kst(st) + (nt2 * 16 + gn + l7) * XS + kb + gk));
                mma16h(sf[nt2 * 2],     qa[ks], bfr);
                mma16h(sf[nt2 * 2 + 1], qa[ks], bfr + 2);
            }
        }

        // ---- softmax (base 2); P overwrites S in place ----
        __half2 h0 = *(__half2*)&sf[0][0];
        __half2 h8 = *(__half2*)&sf[0][1];
        #pragma unroll
        for (int nt = 1; nt < 16; nt++) {
            h0 = __hmax2(h0, *(__half2*)&sf[nt][0]);
            h8 = __hmax2(h8, *(__half2*)&sf[nt][1]);
        }
        float mx0 = fmaxf(__low2float(h0), __high2float(h0));
        float mx8 = fmaxf(__low2float(h8), __high2float(h8));
        mx0 = fmaxf(mx0, __shfl_xor_sync(0xffffffffu, mx0, 1));
        mx0 = fmaxf(mx0, __shfl_xor_sync(0xffffffffu, mx0, 2));
        mx8 = fmaxf(mx8, __shfl_xor_sync(0xffffffffu, mx8, 1));
        mx8 = fmaxf(mx8, __shfl_xor_sync(0xffffffffu, mx8, 2));
        float nm0 = fmaxf(mx0, m0);
        float nm8 = fmaxf(mx8, m8);

        __half2 mh0 = __float2half2_rn(nm0);
        __half2 mh8 = __float2half2_rn(nm8);
        float sum0 = 0.0f, sum8 = 0.0f;
        #pragma unroll
        for (int nt = 0; nt < 16; nt++) {
            __half2 d0 = __hsub2(*(__half2*)&sf[nt][0], mh0);
            __half2 d8 = __hsub2(*(__half2*)&sf[nt][1], mh8);
            uint32_t p01 = ex2h2(*(uint32_t*)&d0);
            uint32_t p23 = ex2h2(*(uint32_t*)&d8);
            sf[nt][0] = p01; sf[nt][1] = p23;
            float2 f01 = __half22float2(*(__half2*)&p01);
            float2 f23 = __half22float2(*(__half2*)&p23);
            sum0 += f01.x + f01.y;
            sum8 += f23.x + f23.y;
        }

        bool resc = !__all_sync(0xffffffffu, (nm0 == m0) & (nm8 == m8));
        if (resc) {
            float corr0 = ex2f(m0 - nm0);
            float corr8 = ex2f(m8 - nm8);
            l0  = l0  * corr0 + sum0;
            l8v = l8v * corr8 + sum8;
            #pragma unroll
            for (int nt = 0; nt < 8; nt++) {
                o_acc[nt][0] *= corr0; o_acc[nt][1] *= corr0;
                o_acc[nt][2] *= corr8; o_acc[nt][3] *= corr8;
            }
        } else { l0 += sum0; l8v += sum8; }
        m0 = nm0; m8 = nm8;

        // ---- PV: k=128, A-fragments are the in-place P halves ----
        #pragma unroll
        for (int ks2 = 0; ks2 < 8; ks2++) {
            const int kb = ks2 * 16;
            uint32_t a[4] = { sf[2 * ks2][0],     sf[2 * ks2][1],
                              sf[2 * ks2 + 1][0], sf[2 * ks2 + 1][1] };
            #pragma unroll
            for (int nt2 = 0; nt2 < 4; nt2++) {
                uint32_t bfr[4];
                ldmx4t(bfr, su(Vst(st) + (kb + gk + l7) * XS + nt2 * 16 + gn));
                mma16(o_acc[nt2 * 2],     a, bfr);
                mma16(o_acc[nt2 * 2 + 1], a, bfr + 2);
            }
        }
    }

    // ---- epilogue ----
    l0  += __shfl_xor_sync(0xffffffffu, l0, 1);
    l0  += __shfl_xor_sync(0xffffffffu, l0, 2);
    l8v += __shfl_xor_sync(0xffffffffu, l8v, 1);
    l8v += __shfl_xor_sync(0xffffffffu, l8v, 2);
    float inv0 = 1.0f / l0, inv8 = 1.0f / l8v;
    #pragma unroll
    for (int nt = 0; nt < 8; nt++) {
        int col = nt * 8 + 2 * lt;
        *(uint32_t*)&g_O[((size_t)bn * HW + qrow) * DHEAD + col] =
            pack2(o_acc[nt][0] * inv0, o_acc[nt][1] * inv0);
        *(uint32_t*)&g_O[((size_t)bn * HW + qrow + 8) * DHEAD + col] =
            pack2(o_acc[nt][2] * inv8, o_acc[nt][3] * inv8);
    }
}

// ---------------------------------------------------------------------------
// Kernel 3: output projection. 512 threads (16 warps, 4m x 4n; warp tile
// 32c x 32s). Tile 128c x 128s, BK=64 (one head), 8 k-iters, 3-stage ring.
// grid (18, 4, 2) = 144.
// ---------------------------------------------------------------------------
#define PROJ_STG_H (2 * 128 * XS)                // 18432 halfs
#define PROJ_SMEM_BYTES (3 * PROJ_STG_H * 2)     // 110592

__global__ __launch_bounds__(512, 1) void proj_kernel(
    const float* __restrict__ bo, float* __restrict__ out)
{
    extern __shared__ __half smP[];

    const int b  = blockIdx.z;
    const int c0 = blockIdx.y * 128;
    const int s0 = blockIdx.x * 128;
    const int tid    = threadIdx.x;
    const int wid    = tid >> 5;
    const int lane   = tid & 31;
    const int lg     = lane >> 2;
    const int lt     = lane & 3;
    const int l7     = lane & 7;
    const int l8     = (lane >> 3) & 1;
    const int l16    = lane >> 4;
    const int g      = lane >> 3;
    const int gk     = (g & 1) << 3;
    const int gn     = (g >> 1) << 3;
    const int warp_m = wid >> 2;   // c (x32)
    const int warp_n = wid & 3;    // s (x32)

    float acc[2][4][4] = {};       // [mi][nt][frag]

    auto Wst = [&](int st) { return smP + st * PROJ_STG_H; };
    auto Ast = [&](int st) { return smP + st * PROJ_STG_H + 128 * XS; };

    auto load_chunk = [&](int st, int kc) {
        #pragma unroll
        for (int t = 0; t < 4; t++) {
            int idx = tid + t * 512;
            int row = (idx >> 3) & 127, seg = idx & 7;
            if (idx < 1024)
                cp16(su(Wst(st) + row * XS + seg * 8),
                     &g_Wot[(size_t)(c0 + row) * C_DIM + kc * 64 + seg * 8]);
            else
                cp16(su(Ast(st) + row * XS + seg * 8),
                     &g_O[((size_t)(b * HEADS + kc) * HW + s0 + row) * DHEAD + seg * 8]);
        }
    };

    load_chunk(0, 0); CP_COMMIT();
    load_chunk(1, 1); CP_COMMIT();

    for (int kc = 0; kc < 8; kc++) {
        const int st = kc % 3;
        CP_WAIT1();
        __syncthreads();
        if (kc + 2 < 8) load_chunk((kc + 2) % 3, kc + 2);
        CP_COMMIT();

        #pragma unroll
        for (int ks = 0; ks < 4; ks++) {
            const int kb = ks * 16;
            uint32_t a[2][4];
            #pragma unroll
            for (int mi = 0; mi < 2; mi++)
                ldmx4(a[mi], su(Wst(st) + (warp_m * 32 + mi * 16 + l8 * 8 + l7) * XS
                                + kb + l16 * 8));
            #pragma unroll
            for (int nt2 = 0; nt2 < 2; nt2++) {
                uint32_t bfr[4];
                ldmx4(bfr, su(Ast(st) + (warp_n * 32 + nt2 * 16 + gn + l7) * XS
                              + kb + gk));
                #pragma unroll
                for (int mi = 0; mi < 2; mi++) {
                    mma16(acc[mi][nt2 * 2],     a[mi], bfr);
                    mma16(acc[mi][nt2 * 2 + 1], a[mi], bfr + 2);
                }
            }
        }
    }

    #pragma unroll
    for (int mi = 0; mi < 2; mi++) {
        const int crow = c0 + warp_m * 32 + mi * 16 + lg;
        const float bias0 = bo[crow];
        const float bias8 = bo[crow + 8];
        #pragma unroll
        for (int nt = 0; nt < 4; nt++) {
            int s = s0 + warp_n * 32 + nt * 8 + 2 * lt;
            *(float2*)&out[((size_t)b * C_DIM + crow) * HW + s] =
                make_float2(acc[mi][nt][0] + bias0, acc[mi][nt][1] + bias0);
            *(float2*)&out[((size_t)b * C_DIM + crow + 8) * HW + s] =
                make_float2(acc[mi][nt][2] + bias8, acc[mi][nt][3] + bias8);
        }
    }
}

// ---------------------------------------------------------------------------
extern "C" void kernel_launch(void* const* d_in, const int* in_sizes, int n_in,
                              void* d_out, int out_size)
{
    const float* X  = (const float*)d_in[0];
    const float* Wq = (const float*)d_in[1];
    const float* bq = (const float*)d_in[2];
    const float* Wk = (const float*)d_in[3];
    const float* bk = (const float*)d_in[4];
    const float* Wv = (const float*)d_in[5];
    const float* bv = (const float*)d_in[6];
    const float* Wo = (const float*)d_in[7];
    const float* bo = (const float*)d_in[8];
    float* out = (float*)d_out;

    cudaFuncSetAttribute(qkv_kernel,
                         cudaFuncAttributeMaxDynamicSharedMemorySize,
                         QKV_SMEM_BYTES);
    cudaFuncSetAttribute(attn_kernel,
                         cudaFuncAttributeMaxDynamicSharedMemorySize,
                         ATTN_SMEM_BYTES);
    cudaFuncSetAttribute(proj_kernel,
                         cudaFuncAttributeMaxDynamicSharedMemorySize,
                         PROJ_SMEM_BYTES);

    cvt_kernel<<<(NCVT / 8 + 255) / 256, 256>>>(X, Wq, Wk, Wv, Wo);
    qkv_kernel<<<dim3(HW / 128, BN), 256, QKV_SMEM_BYTES>>>(bq, bk, bv);
    attn_kernel<<<dim3(HW / QT, BN), 512, ATTN_SMEM_BYTES>>>();
    proj_kernel<<<dim3(HW / 128, C_DIM / 128, BATCH), 512, PROJ_SMEM_BYTES>>>(bo, out);
}

// round 15
// speedup vs baseline: 1.0317x; 1.0317x over previous
#include <cuda_runtime.h>
#include <cuda_fp16.h>
#include <stdint.h>

#define HEADS   8
#define DHEAD   64
#define C_DIM   512
#define BATCH   2
#define HW      2304          // 48*48
#define BN      (BATCH*HEADS) // 16
#define KCH     64            // kv chunk rows in attention
#define NCH     (HW / KCH)    // 36
#define QT      256           // q-tile rows in attention

// Scratch (no cudaMalloc allowed). All fp16.
__device__ __align__(16) __half g_Q[BN * HW * DHEAD];
__device__ __align__(16) __half g_K[BN * HW * DHEAD];
__device__ __align__(16) __half g_V[BN * HW * DHEAD];
__device__ __align__(16) __half g_O[BN * HW * DHEAD];
__device__ __align__(16) __half g_Xt[BATCH * C_DIM * HW];         // X as fp16
__device__ __align__(16) __half g_Wt[3 * HEADS * DHEAD * C_DIM];  // Wq|Wk|Wv fp16
__device__ __align__(16) __half g_Wot[C_DIM * C_DIM];             // Wo fp16

#define NX   (BATCH * C_DIM * HW)        // 2359296
#define NW   (HEADS * DHEAD * C_DIM)     // 262144
#define NWO  (C_DIM * C_DIM)             // 262144
#define NCVT (NX + 3 * NW + NWO)

#define LOG2E 1.44269504088896340736f

// ---------------------------------------------------------------------------
// helpers
// ---------------------------------------------------------------------------
__device__ __forceinline__ uint32_t pack2(float a, float b) {
    __half2 h = __floats2half2_rn(a, b);
    return *(uint32_t*)&h;
}
__device__ __forceinline__ float ex2f(float x) {
    float y; asm("ex2.approx.f32 %0, %1;" : "=f"(y) : "f"(x)); return y;
}
__device__ __forceinline__ uint32_t ex2h2(uint32_t x) {
    uint32_t y; asm("ex2.approx.f16x2 %0, %1;" : "=r"(y) : "r"(x)); return y;
}
__device__ __forceinline__ void mma16(float* c, const uint32_t* a, const uint32_t* b) {
    asm volatile(
        "mma.sync.aligned.m16n8k16.row.col.f32.f16.f16.f32 "
        "{%0,%1,%2,%3}, {%4,%5,%6,%7}, {%8,%9}, {%0,%1,%2,%3};"
        : "+f"(c[0]), "+f"(c[1]), "+f"(c[2]), "+f"(c[3])
        : "r"(a[0]), "r"(a[1]), "r"(a[2]), "r"(a[3]), "r"(b[0]), "r"(b[1]));
}
__device__ __forceinline__ void mma16h(uint32_t* c, const uint32_t* a, const uint32_t* b) {
    asm volatile(
        "mma.sync.aligned.m16n8k16.row.col.f16.f16.f16.f16 "
        "{%0,%1}, {%2,%3,%4,%5}, {%6,%7}, {%0,%1};"
        : "+r"(c[0]), "+r"(c[1])
        : "r"(a[0]), "r"(a[1]), "r"(a[2]), "r"(a[3]), "r"(b[0]), "r"(b[1]));
}
__device__ __forceinline__ uint32_t su(const void* p) {
    return (uint32_t)__cvta_generic_to_shared(p);
}
__device__ __forceinline__ void ldmx4(uint32_t* r, uint32_t a) {
    asm volatile("ldmatrix.sync.aligned.m8n8.x4.shared.b16 {%0,%1,%2,%3}, [%4];"
                 : "=r"(r[0]), "=r"(r[1]), "=r"(r[2]), "=r"(r[3]) : "r"(a));
}
__device__ __forceinline__ void ldmx4t(uint32_t* r, uint32_t a) {
    asm volatile("ldmatrix.sync.aligned.m8n8.x4.trans.shared.b16 {%0,%1,%2,%3}, [%4];"
                 : "=r"(r[0]), "=r"(r[1]), "=r"(r[2]), "=r"(r[3]) : "r"(a));
}
__device__ __forceinline__ void cp16(uint32_t dst, const void* src) {
    asm volatile("cp.async.cg.shared.global [%0], [%1], 16;"
                 :: "r"(dst), "l"(src) : "memory");
}
#define CP_COMMIT() asm volatile("cp.async.commit_group;" ::: "memory")
#define CP_WAIT1()  asm volatile("cp.async.wait_group 1;" ::: "memory")
#define CP_WAIT2()  asm volatile("cp.async.wait_group 2;" ::: "memory")

#define XS 72    // 64-wide rows: 64 + 8 pad (halfs)
#define XQ 136   // qkv X rows: 128 + 8 pad (halfs)

// ---------------------------------------------------------------------------
// Kernel 0: one-time fp16 conversion of X, Wq|Wk|Wv, Wo. 8 elems/thread.
// ---------------------------------------------------------------------------
__global__ __launch_bounds__(256) void cvt_kernel(
    const float* __restrict__ X,
    const float* __restrict__ Wq, const float* __restrict__ Wk,
    const float* __restrict__ Wv, const float* __restrict__ Wo)
{
    int i = (blockIdx.x * 256 + threadIdx.x) * 8;
    if (i >= NCVT) return;
    const float* src;
    __half* dst;
    int j;
    if (i < NX)               { src = X;  dst = g_Xt;           j = i; }
    else if (i < NX + NW)     { src = Wq; dst = g_Wt;           j = i - NX; }
    else if (i < NX + 2 * NW) { src = Wk; dst = g_Wt + NW;      j = i - NX - NW; }
    else if (i < NX + 3 * NW) { src = Wv; dst = g_Wt + 2 * NW;  j = i - NX - 2 * NW; }
    else                      { src = Wo; dst = g_Wot;          j = i - NX - 3 * NW; }
    float4 v0 = *(const float4*)&src[j];
    float4 v1 = *(const float4*)&src[j + 4];
    uint4 h = make_uint4(pack2(v0.x, v0.y), pack2(v0.z, v0.w),
                         pack2(v1.x, v1.y), pack2(v1.z, v1.w));
    *(uint4*)&dst[j] = h;
}

// ---------------------------------------------------------------------------
// Kernel 1: merged QKV projection (unchanged from R13/R14).
// Tile 128(s) x 192(d), BK=64, 8 k-iters, 3-stage ring, 256 threads.
// ---------------------------------------------------------------------------
#define QKV_STG_H (64 * XQ + 3 * 64 * XS)       // 22528 halfs
#define QKV_SMEM_BYTES (3 * QKV_STG_H * 2)      // 135168

__global__ __launch_bounds__(256, 1) void qkv_kernel(
    const float* __restrict__ bq, const float* __restrict__ bk,
    const float* __restrict__ bv)
{
    extern __shared__ __half sm[];

    const int bn = blockIdx.y;
    const int b  = bn >> 3;
    const int n  = bn & 7;
    const int s0 = blockIdx.x * 128;

    const int tid    = threadIdx.x;
    const int wid    = tid >> 5;
    const int lane   = tid & 31;
    const int lg     = lane >> 2;
    const int lt     = lane & 3;
    const int warp_m = wid >> 1;
    const int warp_n = wid & 1;
    const int l7     = lane & 7;
    const int l8     = (lane >> 3) & 1;
    const int l16    = lane >> 4;
    const int g      = lane >> 3;
    const int gk     = (g & 1) << 3;
    const int gn     = (g >> 1) << 3;

    float acc[3][2][4][4] = {};

    auto Xst = [&](int st) { return sm + st * QKV_STG_H; };
    auto Wst = [&](int st, int w) { return sm + st * QKV_STG_H + 64 * XQ + w * 64 * XS; };

    auto load_chunk = [&](int st, int kc) {
        const int k0 = kc * 64;
        #pragma unroll
        for (int t = 0; t < 10; t++) {
            int idx = tid + t * 256;
            if (idx < 1024) {
                int kk = idx >> 4, seg = idx & 15;
                cp16(su(Xst(st) + kk * XQ + seg * 8),
                     &g_Xt[((size_t)b * C_DIM + k0 + kk) * HW + s0 + seg * 8]);
            } else {
                int j = idx - 1024;
                int w = j >> 9, r = j & 511;
                int d = r >> 3, seg = r & 7;
                cp16(su(Wst(st, w) + d * XS + seg * 8),
                     &g_Wt[(size_t)w * NW + ((size_t)n * DHEAD + d) * C_DIM + k0 + seg * 8]);
            }
        }
    };

    load_chunk(0, 0); CP_COMMIT();
    load_chunk(1, 1); CP_COMMIT();

    for (int kc = 0; kc < 8; kc++) {
        const int st = kc % 3;
        CP_WAIT1();
        __syncthreads();
        if (kc + 2 < 8) load_chunk((kc + 2) % 3, kc + 2);
        CP_COMMIT();

        #pragma unroll
        for (int ks = 0; ks < 4; ks++) {
            const int kb = ks * 16;
            uint32_t a[2][4];
            #pragma unroll
            for (int mi = 0; mi < 2; mi++)
                ldmx4t(a[mi], su(Xst(st) + (kb + l16 * 8 + l7) * XQ
                                 + warp_m * 32 + mi * 16 + l8 * 8));
            #pragma unroll
            for (int w = 0; w < 3; w++) {
                #pragma unroll
                for (int nt2 = 0; nt2 < 2; nt2++) {
                    uint32_t bfr[4];
                    ldmx4(bfr, su(Wst(st, w)
                                  + (warp_n * 32 + nt2 * 16 + gn + l7) * XS
                                  + kb + gk));
                    #pragma unroll
                    for (int mi = 0; mi < 2; mi++) {
                        mma16(acc[w][mi][nt2 * 2],     a[mi], bfr);
                        mma16(acc[w][mi][nt2 * 2 + 1], a[mi], bfr + 2);
                    }
                }
            }
        }
    }

    const float* bp[3] = {bq, bk, bv};
    __half* Outp[3] = {g_Q, g_K, g_V};
    #pragma unroll
    for (int w = 0; w < 3; w++) {
        const float scale = (w == 0) ? 0.125f * LOG2E : 1.0f;
        __half* Out = Outp[w];
        #pragma unroll
        for (int mi = 0; mi < 2; mi++) {
            const int row0 = s0 + warp_m * 32 + mi * 16 + lg;
            #pragma unroll
            for (int nt = 0; nt < 4; nt++) {
                int col = warp_n * 32 + nt * 8 + 2 * lt;
                float b0f = bp[w][n * DHEAD + col];
                float b1f = bp[w][n * DHEAD + col + 1];
                *(uint32_t*)&Out[((size_t)bn * HW + row0) * DHEAD + col] =
                    pack2((acc[w][mi][nt][0] + b0f) * scale,
                          (acc[w][mi][nt][1] + b1f) * scale);
                *(uint32_t*)&Out[((size_t)bn * HW + row0 + 8) * DHEAD + col] =
                    pack2((acc[w][mi][nt][2] + b0f) * scale,
                          (acc[w][mi][nt][3] + b1f) * scale);
            }
        }
    }
}

// ---------------------------------------------------------------------------
// Kernel 2: flash attention. 512 threads, QT=256 (16 warps x 16 rows),
// KCH=64 (36 chunks), 4-stage ring, cross-chunk pipeline (S(kt+1) between
// softmax(kt) and PV(kt)), f16 S accumulators, log2 softmax, register P.
// grid (9, 16) = 144 CTAs = one wave.
// ---------------------------------------------------------------------------
#define ATTN_STG_H (2 * KCH * XS)                 // 9216 halfs (K+V)
#define ATTN_SMEM_BYTES (4 * ATTN_STG_H * 2)      // 73728

__global__ __launch_bounds__(512, 1) void attn_kernel()
{
    extern __shared__ __half smA[];
    const int bn = blockIdx.y;
    const int q0 = blockIdx.x * QT;
    const int tid = threadIdx.x, wid = tid >> 5, lane = tid & 31;
    const int lg = lane >> 2, lt = lane & 3, l7 = lane & 7;
    const int g = lane >> 3, gk = (g & 1) << 3, gn = (g >> 1) << 3;
    const int qrow = q0 + wid * 16 + lg;

    auto Kst = [&](int st) { return smA + st * ATTN_STG_H; };
    auto Vst = [&](int st) { return smA + st * ATTN_STG_H + KCH * XS; };

    // ---- Q fragments register-resident (pre-scaled fp16, log2 domain) ----
    uint32_t qa[4][4];
    {
        const __half* Qb = &g_Q[((size_t)bn * HW + qrow) * DHEAD];
        #pragma unroll
        for (int ks = 0; ks < 4; ks++) {
            int k = ks * 16 + 2 * lt;
            qa[ks][0] = *(const uint32_t*)&Qb[k];
            qa[ks][1] = *(const uint32_t*)&Qb[8 * DHEAD + k];
            qa[ks][2] = *(const uint32_t*)&Qb[k + 8];
            qa[ks][3] = *(const uint32_t*)&Qb[8 * DHEAD + k + 8];
        }
    }

    auto load_chunk = [&](int st, int kt) {
        // K,V: 64 rows x 8 segs = 512 each -> 1024 segs, 2/thread
        #pragma unroll
        for (int t = 0; t < 2; t++) {
            int idx = tid + t * 512;
            int r = (idx >> 3) & 63, seg = idx & 7;
            const __half* src = (idx < 512 ? g_K : g_V)
                              + ((size_t)bn * HW + (size_t)kt * KCH + r) * DHEAD + seg * 8;
            cp16(su((idx < 512 ? Kst(st) : Vst(st)) + r * XS + seg * 8), src);
        }
    };

    auto computeS = [&](int st, uint32_t (&sf)[8][2]) {
        #pragma unroll
        for (int nt = 0; nt < 8; nt++) { sf[nt][0] = 0u; sf[nt][1] = 0u; }
        #pragma unroll
        for (int ks = 0; ks < 4; ks++) {
            const int kb = ks * 16;
            #pragma unroll
            for (int nt2 = 0; nt2 < 4; nt2++) {
                uint32_t bfr[4];
                ldmx4(bfr, su(Kst(st) + (nt2 * 16 + gn + l7) * XS + kb + gk));
                mma16h(sf[nt2 * 2],     qa[ks], bfr);
                mma16h(sf[nt2 * 2 + 1], qa[ks], bfr + 2);
            }
        }
    };

    load_chunk(0, 0); CP_COMMIT();
    load_chunk(1, 1); CP_COMMIT();
    load_chunk(2, 2); CP_COMMIT();

    float o_acc[8][4] = {};
    float m0 = -1e30f, m8 = -1e30f, l0 = 0.0f, l8v = 0.0f;

    uint32_t sfA[8][2], sfB[8][2];

    // prologue: chunk 0 ready, compute S(0)
    CP_WAIT2();
    __syncthreads();
    computeS(0, sfA);

    auto step = [&](int kt, uint32_t (&cur)[8][2], uint32_t (&nxt)[8][2]) {
        CP_WAIT1();            // chunk kt+1 complete
        __syncthreads();
        if (kt + 3 < NCH) load_chunk((kt + 3) & 3, kt + 3);
        CP_COMMIT();

        // ---- softmax on cur (f16 packed, base-2) ----
        __half2 h0 = *(__half2*)&cur[0][0];
        __half2 h8 = *(__half2*)&cur[0][1];
        #pragma unroll
        for (int nt = 1; nt < 8; nt++) {
            h0 = __hmax2(h0, *(__half2*)&cur[nt][0]);
            h8 = __hmax2(h8, *(__half2*)&cur[nt][1]);
        }
        float mx0 = fmaxf(__low2float(h0), __high2float(h0));
        float mx8 = fmaxf(__low2float(h8), __high2float(h8));
        mx0 = fmaxf(mx0, __shfl_xor_sync(0xffffffffu, mx0, 1));
        mx0 = fmaxf(mx0, __shfl_xor_sync(0xffffffffu, mx0, 2));
        mx8 = fmaxf(mx8, __shfl_xor_sync(0xffffffffu, mx8, 1));
        mx8 = fmaxf(mx8, __shfl_xor_sync(0xffffffffu, mx8, 2));
        float nm0 = fmaxf(mx0, m0);
        float nm8 = fmaxf(mx8, m8);

        __half2 mh0 = __float2half2_rn(nm0);
        __half2 mh8 = __float2half2_rn(nm8);
        uint32_t pa[8][2];
        float sum0 = 0.0f, sum8 = 0.0f;
        #pragma unroll
        for (int nt = 0; nt < 8; nt++) {
            __half2 d0 = __hsub2(*(__half2*)&cur[nt][0], mh0);
            __half2 d8 = __hsub2(*(__half2*)&cur[nt][1], mh8);
            uint32_t p01 = ex2h2(*(uint32_t*)&d0);
            uint32_t p23 = ex2h2(*(uint32_t*)&d8);
            pa[nt][0] = p01; pa[nt][1] = p23;
            float2 f01 = __half22float2(*(__half2*)&p01);
            float2 f23 = __half22float2(*(__half2*)&p23);
            sum0 += f01.x + f01.y;
            sum8 += f23.x + f23.y;
        }

        bool resc = !__all_sync(0xffffffffu, (nm0 == m0) & (nm8 == m8));
        if (resc) {
            float corr0 = ex2f(m0 - nm0);
            float corr8 = ex2f(m8 - nm8);
            l0  = l0  * corr0 + sum0;
            l8v = l8v * corr8 + sum8;
            #pragma unroll
            for (int nt = 0; nt < 8; nt++) {
                o_acc[nt][0] *= corr0; o_acc[nt][1] *= corr0;
                o_acc[nt][2] *= corr8; o_acc[nt][3] *= corr8;
            }
        } else { l0 += sum0; l8v += sum8; }
        m0 = nm0; m8 = nm8;

        // ---- S(kt+1): fills tensor pipe while softmax/MUFU retires ----
        if (kt + 1 < NCH) computeS((kt + 1) & 3, nxt);

        // ---- PV(kt) ----
        const int st = kt & 3;
        #pragma unroll
        for (int ks2 = 0; ks2 < 4; ks2++) {
            const int kb = ks2 * 16;
            uint32_t a[4] = { pa[2 * ks2][0],     pa[2 * ks2][1],
                              pa[2 * ks2 + 1][0], pa[2 * ks2 + 1][1] };
            #pragma unroll
            for (int nt2 = 0; nt2 < 4; nt2++) {
                uint32_t bfr[4];
                ldmx4t(bfr, su(Vst(st) + (kb + gk + l7) * XS + nt2 * 16 + gn));
                mma16(o_acc[nt2 * 2],     a, bfr);
                mma16(o_acc[nt2 * 2 + 1], a, bfr + 2);
            }
        }
    };

    #pragma unroll 1
    for (int k2 = 0; k2 < NCH; k2 += 2) {
        step(k2,     sfA, sfB);
        step(k2 + 1, sfB, sfA);
    }

    // ---- epilogue ----
    l0  += __shfl_xor_sync(0xffffffffu, l0, 1);
    l0  += __shfl_xor_sync(0xffffffffu, l0, 2);
    l8v += __shfl_xor_sync(0xffffffffu, l8v, 1);
    l8v += __shfl_xor_sync(0xffffffffu, l8v, 2);
    float inv0 = 1.0f / l0, inv8 = 1.0f / l8v;
    #pragma unroll
    for (int nt = 0; nt < 8; nt++) {
        int col = nt * 8 + 2 * lt;
        *(uint32_t*)&g_O[((size_t)bn * HW + qrow) * DHEAD + col] =
            pack2(o_acc[nt][0] * inv0, o_acc[nt][1] * inv0);
        *(uint32_t*)&g_O[((size_t)bn * HW + qrow + 8) * DHEAD + col] =
            pack2(o_acc[nt][2] * inv8, o_acc[nt][3] * inv8);
    }
}

// ---------------------------------------------------------------------------
// Kernel 3: output projection (unchanged from R14). 512 threads, 16 warps
// (4m x 4n, warp tile 32c x 32s), tile 128c x 128s, BK=64, 3-stage ring.
// grid (18, 4, 2) = 144.
// ---------------------------------------------------------------------------
#define PROJ_STG_H (2 * 128 * XS)                // 18432 halfs
#define PROJ_SMEM_BYTES (3 * PROJ_STG_H * 2)     // 110592

__global__ __launch_bounds__(512, 1) void proj_kernel(
    const float* __restrict__ bo, float* __restrict__ out)
{
    extern __shared__ __half smP[];

    const int b  = blockIdx.z;
    const int c0 = blockIdx.y * 128;
    const int s0 = blockIdx.x * 128;
    const int tid    = threadIdx.x;
    const int wid    = tid >> 5;
    const int lane   = tid & 31;
    const int lg     = lane >> 2;
    const int lt     = lane & 3;
    const int l7     = lane & 7;
    const int l8     = (lane >> 3) & 1;
    const int l16    = lane >> 4;
    const int g      = lane >> 3;
    const int gk     = (g & 1) << 3;
    const int gn     = (g >> 1) << 3;
    const int warp_m = wid >> 2;   // c (x32)
    const int warp_n = wid & 3;    // s (x32)

    float acc[2][4][4] = {};

    auto Wst = [&](int st) { return smP + st * PROJ_STG_H; };
    auto Ast = [&](int st) { return smP + st * PROJ_STG_H + 128 * XS; };

    auto load_chunk = [&](int st, int kc) {
        #pragma unroll
        for (int t = 0; t < 4; t++) {
            int idx = tid + t * 512;
            int row = (idx >> 3) & 127, seg = idx & 7;
            if (idx < 1024)
                cp16(su(Wst(st) + row * XS + seg * 8),
                     &g_Wot[(size_t)(c0 + row) * C_DIM + kc * 64 + seg * 8]);
            else
                cp16(su(Ast(st) + row * XS + seg * 8),
                     &g_O[((size_t)(b * HEADS + kc) * HW + s0 + row) * DHEAD + seg * 8]);
        }
    };

    load_chunk(0, 0); CP_COMMIT();
    load_chunk(1, 1); CP_COMMIT();

    for (int kc = 0; kc < 8; kc++) {
        const int st = kc % 3;
        CP_WAIT1();
        __syncthreads();
        if (kc + 2 < 8) load_chunk((kc + 2) % 3, kc + 2);
        CP_COMMIT();

        #pragma unroll
        for (int ks = 0; ks < 4; ks++) {
            const int kb = ks * 16;
            uint32_t a[2][4];
            #pragma unroll
            for (int mi = 0; mi < 2; mi++)
                ldmx4(a[mi], su(Wst(st) + (warp_m * 32 + mi * 16 + l8 * 8 + l7) * XS
                                + kb + l16 * 8));
            #pragma unroll
            for (int nt2 = 0; nt2 < 2; nt2++) {
                uint32_t bfr[4];
                ldmx4(bfr, su(Ast(st) + (warp_n * 32 + nt2 * 16 + gn + l7) * XS
                              + kb + gk));
                #pragma unroll
                for (int mi = 0; mi < 2; mi++) {
                    mma16(acc[mi][nt2 * 2],     a[mi], bfr);
                    mma16(acc[mi][nt2 * 2 + 1], a[mi], bfr + 2);
                }
            }
        }
    }

    #pragma unroll
    for (int mi = 0; mi < 2; mi++) {
        const int crow = c0 + warp_m * 32 + mi * 16 + lg;
        const float bias0 = bo[crow];
        const float bias8 = bo[crow + 8];
        #pragma unroll
        for (int nt = 0; nt < 4; nt++) {
            int s = s0 + warp_n * 32 + nt * 8 + 2 * lt;
            *(float2*)&out[((size_t)b * C_DIM + crow) * HW + s] =
                make_float2(acc[mi][nt][0] + bias0, acc[mi][nt][1] + bias0);
            *(float2*)&out[((size_t)b * C_DIM + crow + 8) * HW + s] =
                make_float2(acc[mi][nt][2] + bias8, acc[mi][nt][3] + bias8);
        }
    }
}

// ---------------------------------------------------------------------------
extern "C" void kernel_launch(void* const* d_in, const int* in_sizes, int n_in,
                              void* d_out, int out_size)
{
    const float* X  = (const float*)d_in[0];
    const float* Wq = (const float*)d_in[1];
    const float* bq = (const float*)d_in[2];
    const float* Wk = (const float*)d_in[3];
    const float* bk = (const float*)d_in[4];
    const float* Wv = (const float*)d_in[5];
    const float* bv = (const float*)d_in[6];
    const float* Wo = (const float*)d_in[7];
    const float* bo = (const float*)d_in[8];
    float* out = (float*)d_out;

    cudaFuncSetAttribute(qkv_kernel,
                         cudaFuncAttributeMaxDynamicSharedMemorySize,
                         QKV_SMEM_BYTES);
    cudaFuncSetAttribute(attn_kernel,
                         cudaFuncAttributeMaxDynamicSharedMemorySize,
                         ATTN_SMEM_BYTES);
    cudaFuncSetAttribute(proj_kernel,
                         cudaFuncAttributeMaxDynamicSharedMemorySize,
                         PROJ_SMEM_BYTES);

    cvt_kernel<<<(NCVT / 8 + 255) / 256, 256>>>(X, Wq, Wk, Wv, Wo);
    qkv_kernel<<<dim3(HW / 128, BN), 256, QKV_SMEM_BYTES>>>(bq, bk, bv);
    attn_kernel<<<dim3(HW / QT, BN), 512, ATTN_SMEM_BYTES>>>();
    proj_kernel<<<dim3(HW / 128, C_DIM / 128, BATCH), 512, PROJ_SMEM_BYTES>>>(bo, out);
}